// round 9
// baseline (speedup 1.0000x reference)
#include <cuda_runtime.h>
#include <cstdint>

// Problem shape (fixed per reference setup_inputs)
constexpr int Bn = 8;     // batch
constexpr int Tn = 4096;  // xs rows (M)
constexpr int Sn = 256;   // spk rows (N)
constexpr int Dn = 512;   // feature (K)

#define EPS_F 1e-8f

// ---------------------------------------------------------------------------
// Fused kernel: per-batch NT GEMM via TF32 mma.sync + in-register row norms.
// CTA tile 128x128, BK=32, 128 threads (4 warps, 2x2), warp tile 64x64.
// LDS/mma = 1.0. Dynamic smem, stride-36 rows -> conflict-free STS/LDS.
// One __syncthreads per k-tile (16 tiles); producer split in two halves
// interleaved with the mma steps.
// ---------------------------------------------------------------------------
constexpr int BM = 128, BN = 128, BK = 32;
constexpr int SSTR = 36;                 // padded smem row stride (uint32)
constexpr int NT = Dn / BK;              // 16 k-tiles
constexpr int TILE_U32 = BM * SSTR;      // 4608 uint32 per tile buffer

// dynamic smem layout (bytes)
constexpr int SM_A    = 0;                       // uint32[2][TILE_U32]
constexpr int SM_B    = 2 * TILE_U32 * 4;        // 36864
constexpr int SM_INVX = 4 * TILE_U32 * 4;        // 73728 (128 floats)
constexpr int SM_INVY = SM_INVX + BM * 4;        // 74240 (128 floats)
constexpr int SMEM_TOTAL = SM_INVY + BN * 4;     // 74752

__device__ __forceinline__ uint32_t f2tf(float f) {
    uint32_t u;
    asm("cvt.rna.tf32.f32 %0, %1;" : "=r"(u) : "f"(f));
    return u;
}

__device__ __forceinline__ void mma_tf32(float c[4], const uint32_t a[4],
                                         uint32_t b0, uint32_t b1) {
    asm volatile(
        "mma.sync.aligned.m16n8k8.row.col.f32.tf32.tf32.f32 "
        "{%0,%1,%2,%3}, {%4,%5,%6,%7}, {%8,%9}, {%0,%1,%2,%3};"
        : "+f"(c[0]), "+f"(c[1]), "+f"(c[2]), "+f"(c[3])
        : "r"(a[0]), "r"(a[1]), "r"(a[2]), "r"(a[3]), "r"(b0), "r"(b1));
}

__device__ __forceinline__ float dot4(float4 v) {
    return v.x * v.x + v.y * v.y + v.z * v.z + v.w * v.w;
}

__global__ __launch_bounds__(128, 2)
void cos_gemm_w64(const float* __restrict__ X,
                  const float* __restrict__ Y,
                  float* __restrict__ out) {
    extern __shared__ char smraw[];
    uint32_t* As    = reinterpret_cast<uint32_t*>(smraw + SM_A);   // [2][TILE_U32]
    uint32_t* Bs    = reinterpret_cast<uint32_t*>(smraw + SM_B);
    float*    sinvx = reinterpret_cast<float*>(smraw + SM_INVX);
    float*    sinvy = reinterpret_cast<float*>(smraw + SM_INVY);

    const int tid  = threadIdx.x;
    const int b    = blockIdx.z;
    const int mcta = blockIdx.x * BM;
    const int ncta = blockIdx.y * BN;

    const float* A  = X + (size_t)b * Tn * Dn + (size_t)mcta * Dn;
    const float* Bp = Y + (size_t)b * Sn * Dn + (size_t)ncta * Dn;

    // -------- producer mapping -------------------------------------------
    // thread -> (base row r0 = tid>>3 in 0..15, k-quad q = tid&7)
    // covers rows r0 + 16p, p = 0..7; half1: p<4, half2: p>=4.
    const int q  = tid & 7;
    const int r0 = tid >> 3;
    const int lq = q * 4;
    const float* gA = A  + (size_t)r0 * Dn + lq;
    const float* gB = Bp + (size_t)r0 * Dn + lq;
    int soff[8];
    #pragma unroll
    for (int p = 0; p < 8; ++p)
        soff[p] = (r0 + 16 * p) * SSTR + lq;

    // -------- compute mapping: 4 warps in 2x2, warp tile 64x64 ------------
    const int wid  = tid >> 5;
    const int lane = tid & 31;
    const int wm   = wid >> 1;           // 0..1 (M dir, 64 rows)
    const int wn   = wid & 1;            // 0..1 (N dir, 64 cols)
    const int gid  = lane >> 2;          // 0..7
    const int tig  = lane & 3;           // 0..3

    float acc[4][8][4];
    #pragma unroll
    for (int i = 0; i < 4; ++i)
        #pragma unroll
        for (int j = 0; j < 8; ++j)
            #pragma unroll
            for (int p = 0; p < 4; ++p)
                acc[i][j][p] = 0.0f;

    // norm partials for this thread's 8 A rows and 8 B rows (quad q slice)
    float nx[8] = {0, 0, 0, 0, 0, 0, 0, 0};
    float ny[8] = {0, 0, 0, 0, 0, 0, 0, 0};

    float4 ra[4], rb[4];                 // staging for one half (8 float4)

    auto LDGH = [&](int kt, int h) {     // load half h of tile kt
        const int ko = kt * BK;
        #pragma unroll
        for (int p = 0; p < 4; ++p) {
            const size_t roff = (size_t)(16 * (p + 4 * h)) * Dn + ko;
            ra[p] = *reinterpret_cast<const float4*>(gA + roff);
            rb[p] = *reinterpret_cast<const float4*>(gB + roff);
        }
    };
    auto STSH = [&](int buf, int h) {    // store half h + norm accumulation
        uint32_t* Ad = As + buf * TILE_U32;
        uint32_t* Bd = Bs + buf * TILE_U32;
        #pragma unroll
        for (int p = 0; p < 4; ++p) {
            float4 v = ra[p];
            nx[p + 4 * h] += dot4(v);
            uint4 u;
            u.x = f2tf(v.x); u.y = f2tf(v.y); u.z = f2tf(v.z); u.w = f2tf(v.w);
            *reinterpret_cast<uint4*>(&Ad[soff[p + 4 * h]]) = u;
            v = rb[p];
            ny[p + 4 * h] += dot4(v);
            u.x = f2tf(v.x); u.y = f2tf(v.y); u.z = f2tf(v.z); u.w = f2tf(v.w);
            *reinterpret_cast<uint4*>(&Bd[soff[p + 4 * h]]) = u;
        }
    };

    LDGH(0, 0); STSH(0, 0);
    LDGH(0, 1); STSH(0, 1);
    __syncthreads();

    #pragma unroll 1
    for (int kt = 0; kt < NT; ++kt) {
        const int cur = kt & 1;
        const int nxt = cur ^ 1;
        const bool more = (kt + 1 < NT);

        if (more) LDGH(kt + 1, 0);       // prefetch half 1 early

        const uint32_t* __restrict__ Ab = As + cur * TILE_U32;
        const uint32_t* __restrict__ Bb = Bs + cur * TILE_U32;

        #pragma unroll
        for (int s = 0; s < 4; ++s) {    // four k=8 steps per tile
            const int kb = s * 8;
            uint32_t a[4][4];
            #pragma unroll
            for (int i = 0; i < 4; ++i) {
                int r = wm * 64 + i * 16 + gid;
                a[i][0] = Ab[r * SSTR + kb + tig];
                a[i][1] = Ab[(r + 8) * SSTR + kb + tig];
                a[i][2] = Ab[r * SSTR + kb + tig + 4];
                a[i][3] = Ab[(r + 8) * SSTR + kb + tig + 4];
            }
            #pragma unroll
            for (int j = 0; j < 8; ++j) {
                int n0 = wn * 64 + j * 8 + gid;
                uint32_t b0 = Bb[n0 * SSTR + kb + tig];
                uint32_t b1 = Bb[n0 * SSTR + kb + tig + 4];
                #pragma unroll
                for (int i = 0; i < 4; ++i)
                    mma_tf32(acc[i][j], a[i], b0, b1);
            }
            // interleave producer work between the mma step-pairs
            if (s == 1 && more) {
                STSH(nxt, 0);            // writes buffer all warps left last tile
                LDGH(kt + 1, 1);
            }
        }
        if (more) STSH(nxt, 1);
        __syncthreads();
    }

    // -------- finish norms: reduce across the 8 k-quad threads per row ----
    // threads tid = 8*r0 + q (q = tid&7) are contiguous lanes in one warp.
    #pragma unroll
    for (int p = 0; p < 8; ++p) {
        float s = nx[p];
        s += __shfl_xor_sync(0xffffffffu, s, 1);
        s += __shfl_xor_sync(0xffffffffu, s, 2);
        s += __shfl_xor_sync(0xffffffffu, s, 4);
        float t = ny[p];
        t += __shfl_xor_sync(0xffffffffu, t, 1);
        t += __shfl_xor_sync(0xffffffffu, t, 2);
        t += __shfl_xor_sync(0xffffffffu, t, 4);
        if (q == 0) {
            sinvx[r0 + 16 * p] = 1.0f / fmaxf(sqrtf(s), EPS_F);
            sinvy[r0 + 16 * p] = 1.0f / fmaxf(sqrtf(t), EPS_F);
        }
    }
    __syncthreads();

    // -------- epilogue: scale by inverse norms, float2 stores --------
    float* C = out + (size_t)b * Tn * Sn + (size_t)mcta * Sn + ncta;

    #pragma unroll
    for (int i = 0; i < 4; ++i) {
        const int rA = wm * 64 + i * 16 + gid;
        const float sx0 = sinvx[rA];
        const float sx1 = sinvx[rA + 8];
        #pragma unroll
        for (int j = 0; j < 8; ++j) {
            const int c0 = wn * 64 + j * 8 + tig * 2;
            const float sy0 = sinvy[c0];
            const float sy1 = sinvy[c0 + 1];
            float2 w;
            w.x = acc[i][j][0] * sx0 * sy0;
            w.y = acc[i][j][1] * sx0 * sy1;
            *reinterpret_cast<float2*>(&C[(size_t)rA * Sn + c0]) = w;
            w.x = acc[i][j][2] * sx1 * sy0;
            w.y = acc[i][j][3] * sx1 * sy1;
            *reinterpret_cast<float2*>(&C[(size_t)(rA + 8) * Sn + c0]) = w;
        }
    }
}

extern "C" void kernel_launch(void* const* d_in, const int* in_sizes, int n_in,
                              void* d_out, int out_size) {
    const float* xs  = (const float*)d_in[0];   // (8, 4096, 512)
    const float* spk = (const float*)d_in[1];   // (8, 256, 512)
    float* out = (float*)d_out;                 // (8, 4096, 256)

    static bool attr_set = false;
    if (!attr_set) {
        cudaFuncSetAttribute(cos_gemm_w64,
                             cudaFuncAttributeMaxDynamicSharedMemorySize,
                             SMEM_TOTAL);
        attr_set = true;
    }

    dim3 grid(Tn / BM, Sn / BN, Bn);            // (32, 2, 8) = 512 CTAs
    cos_gemm_w64<<<grid, 128, SMEM_TOTAL>>>(xs, spk, out);
}

// round 10
// speedup vs baseline: 1.2921x; 1.2921x over previous
#include <cuda_runtime.h>
#include <cstdint>

// Problem shape (fixed per reference setup_inputs)
constexpr int Bn = 8;     // batch
constexpr int Tn = 4096;  // xs rows (M)
constexpr int Sn = 256;   // spk rows (N)
constexpr int Dn = 512;   // feature (K)

#define EPS_F 1e-8f

// ---------------------------------------------------------------------------
// Fused kernel: per-batch NT GEMM via TF32 mma.sync + row norms from smem.
// CTA tile 128x128, BK=32, 256 threads (8 warps, 4x2), warp tile 32x64.
// cp.async.cg 3-stage gmem->smem pipeline of RAW fp32; cvt.rna at fragment
// load. Stride-36 rows -> conflict-free LDS. One __syncthreads per k-tile.
// ---------------------------------------------------------------------------
constexpr int BM = 128, BN = 128, BK = 32;
constexpr int SSTR = 36;                  // padded smem row stride (u32)
constexpr int NT = Dn / BK;               // 16 k-tiles
constexpr int STAGES = 3;
constexpr int AU32   = BM * SSTR;         // 4608 u32 per A (or B) tile
constexpr int STAGE_U32 = 2 * AU32;       // A then B
constexpr int SM_INVX = STAGES * STAGE_U32 * 4;      // 110592
constexpr int SM_INVY = SM_INVX + BM * 4;            // 111104
constexpr int SMEM_TOTAL = SM_INVY + BN * 4;         // 111616

__device__ __forceinline__ uint32_t f2tf(float f) {
    uint32_t u;
    asm("cvt.rna.tf32.f32 %0, %1;" : "=r"(u) : "f"(f));
    return u;
}
__device__ __forceinline__ uint32_t ldcv(const uint32_t* p) {
    return f2tf(__uint_as_float(*p));
}
__device__ __forceinline__ void mma_tf32(float c[4], const uint32_t a[4],
                                         uint32_t b0, uint32_t b1) {
    asm volatile(
        "mma.sync.aligned.m16n8k8.row.col.f32.tf32.tf32.f32 "
        "{%0,%1,%2,%3}, {%4,%5,%6,%7}, {%8,%9}, {%0,%1,%2,%3};"
        : "+f"(c[0]), "+f"(c[1]), "+f"(c[2]), "+f"(c[3])
        : "r"(a[0]), "r"(a[1]), "r"(a[2]), "r"(a[3]), "r"(b0), "r"(b1));
}
__device__ __forceinline__ float dot4(float4 v) {
    return v.x * v.x + v.y * v.y + v.z * v.z + v.w * v.w;
}
__device__ __forceinline__ void cp16(uint32_t smem, const void* g) {
    asm volatile("cp.async.cg.shared.global [%0], [%1], 16;" :: "r"(smem), "l"(g));
}
__device__ __forceinline__ void cp_commit() {
    asm volatile("cp.async.commit_group;" ::: "memory");
}
template <int N>
__device__ __forceinline__ void cp_wait() {
    asm volatile("cp.async.wait_group %0;" :: "n"(N) : "memory");
}

__global__ __launch_bounds__(256, 2)
void cos_gemm_cp(const float* __restrict__ X,
                 const float* __restrict__ Y,
                 float* __restrict__ out) {
    extern __shared__ char smraw[];
    uint32_t* sbase = reinterpret_cast<uint32_t*>(smraw);
    float* sinvx = reinterpret_cast<float*>(smraw + SM_INVX);
    float* sinvy = reinterpret_cast<float*>(smraw + SM_INVY);
    const uint32_t smadr = (uint32_t)__cvta_generic_to_shared(smraw);

    const int tid  = threadIdx.x;
    const int b    = blockIdx.z;
    const int mcta = blockIdx.x * BM;
    const int ncta = blockIdx.y * BN;

    const float* A  = X + (size_t)b * Tn * Dn + (size_t)mcta * Dn;
    const float* Bp = Y + (size_t)b * Sn * Dn + (size_t)ncta * Dn;

    // -------- producer mapping: 8 x 16B cp.async per thread per tile ------
    // thread -> (base row r0 = tid>>3, k-quad q = tid&7); rows r0 + 32p.
    const int q  = tid & 7;
    const int r0 = tid >> 3;
    const float* gA = A  + (size_t)r0 * Dn + q * 4;
    const float* gB = Bp + (size_t)r0 * Dn + q * 4;
    int soff[4];                           // u32 index within a tile buffer
    #pragma unroll
    for (int p = 0; p < 4; ++p)
        soff[p] = (r0 + 32 * p) * SSTR + q * 4;

    // fill one k-tile into a stage (A half then B half)
    auto FILL = [&](int kt, int stg) {
        const int ko = kt * BK;
        const uint32_t sa = smadr + stg * STAGE_U32 * 4;
        const uint32_t sb = sa + AU32 * 4;
        #pragma unroll
        for (int p = 0; p < 4; ++p) {
            cp16(sa + soff[p] * 4, gA + (size_t)(32 * p) * Dn + ko);
            cp16(sb + soff[p] * 4, gB + (size_t)(32 * p) * Dn + ko);
        }
        cp_commit();
    };

    // -------- compute mapping: 8 warps 4x2, warp tile 32x64 ---------------
    const int wid  = tid >> 5;
    const int lane = tid & 31;
    const int wm   = wid >> 1;            // 0..3 (M dir, 32 rows)
    const int wn   = wid & 1;             // 0..1 (N dir, 64 cols)
    const int gid  = lane >> 2;           // 0..7
    const int tig  = lane & 3;            // 0..3

    float acc[2][8][4];
    #pragma unroll
    for (int i = 0; i < 2; ++i)
        #pragma unroll
        for (int j = 0; j < 8; ++j)
            #pragma unroll
            for (int p = 0; p < 4; ++p)
                acc[i][j][p] = 0.0f;

    float nx[4] = {0, 0, 0, 0}, ny[4] = {0, 0, 0, 0};

    FILL(0, 0);
    FILL(1, 1);

    int stg = 0;
    #pragma unroll 1
    for (int kt = 0; kt < NT; ++kt) {
        if (kt < NT - 1) cp_wait<1>(); else cp_wait<0>();
        __syncthreads();                 // stage kt ready; stage (kt+2)%3 free

        if (kt + 2 < NT) {
            int ns = stg + 2; if (ns >= STAGES) ns -= STAGES;
            FILL(kt + 2, ns);
        }

        const uint32_t* Ab = sbase + stg * STAGE_U32;
        const uint32_t* Bb = Ab + AU32;

        // ---- norms: read back exactly the float4s this thread delivered --
        #pragma unroll
        for (int p = 0; p < 4; ++p) {
            nx[p] += dot4(*reinterpret_cast<const float4*>(Ab + soff[p]));
            ny[p] += dot4(*reinterpret_cast<const float4*>(Bb + soff[p]));
        }

        // ---- 4 k=8 mma steps ----
        #pragma unroll
        for (int s = 0; s < 4; ++s) {
            const int kb = s * 8;
            uint32_t a[2][4];
            #pragma unroll
            for (int i = 0; i < 2; ++i) {
                int r = wm * 32 + i * 16 + gid;
                a[i][0] = ldcv(Ab + r * SSTR + kb + tig);
                a[i][1] = ldcv(Ab + (r + 8) * SSTR + kb + tig);
                a[i][2] = ldcv(Ab + r * SSTR + kb + tig + 4);
                a[i][3] = ldcv(Ab + (r + 8) * SSTR + kb + tig + 4);
            }
            #pragma unroll
            for (int j = 0; j < 8; ++j) {
                int n0 = wn * 64 + j * 8 + gid;
                uint32_t b0 = ldcv(Bb + n0 * SSTR + kb + tig);
                uint32_t b1 = ldcv(Bb + n0 * SSTR + kb + tig + 4);
                mma_tf32(acc[0][j], a[0], b0, b1);
                mma_tf32(acc[1][j], a[1], b0, b1);
            }
        }

        ++stg; if (stg >= STAGES) stg -= STAGES;
        __syncthreads();                 // done reading stage before refill wraps
    }

    // -------- finish norms: reduce across the 8 k-quad threads per row ----
    #pragma unroll
    for (int p = 0; p < 4; ++p) {
        float s = nx[p];
        s += __shfl_xor_sync(0xffffffffu, s, 1);
        s += __shfl_xor_sync(0xffffffffu, s, 2);
        s += __shfl_xor_sync(0xffffffffu, s, 4);
        float t = ny[p];
        t += __shfl_xor_sync(0xffffffffu, t, 1);
        t += __shfl_xor_sync(0xffffffffu, t, 2);
        t += __shfl_xor_sync(0xffffffffu, t, 4);
        if (q == 0) {
            sinvx[r0 + 32 * p] = 1.0f / fmaxf(sqrtf(s), EPS_F);
            sinvy[r0 + 32 * p] = 1.0f / fmaxf(sqrtf(t), EPS_F);
        }
    }
    __syncthreads();

    // -------- epilogue: scale by inverse norms, float2 stores --------
    float* C = out + (size_t)b * Tn * Sn + (size_t)mcta * Sn + ncta;

    #pragma unroll
    for (int i = 0; i < 2; ++i) {
        const int rA = wm * 32 + i * 16 + gid;
        const float sx0 = sinvx[rA];
        const float sx1 = sinvx[rA + 8];
        #pragma unroll
        for (int j = 0; j < 8; ++j) {
            const int c0 = wn * 64 + j * 8 + tig * 2;
            const float sy0 = sinvy[c0];
            const float sy1 = sinvy[c0 + 1];
            float2 w;
            w.x = acc[i][j][0] * sx0 * sy0;
            w.y = acc[i][j][1] * sx0 * sy1;
            *reinterpret_cast<float2*>(&C[(size_t)rA * Sn + c0]) = w;
            w.x = acc[i][j][2] * sx1 * sy0;
            w.y = acc[i][j][3] * sx1 * sy1;
            *reinterpret_cast<float2*>(&C[(size_t)(rA + 8) * Sn + c0]) = w;
        }
    }
}

extern "C" void kernel_launch(void* const* d_in, const int* in_sizes, int n_in,
                              void* d_out, int out_size) {
    const float* xs  = (const float*)d_in[0];   // (8, 4096, 512)
    const float* spk = (const float*)d_in[1];   // (8, 256, 512)
    float* out = (float*)d_out;                 // (8, 4096, 256)

    static bool attr_set = false;
    if (!attr_set) {
        cudaFuncSetAttribute(cos_gemm_cp,
                             cudaFuncAttributeMaxDynamicSharedMemorySize,
                             SMEM_TOTAL);
        attr_set = true;
    }

    dim3 grid(Tn / BM, Sn / BN, Bn);            // (32, 2, 8) = 512 CTAs
    cos_gemm_cp<<<grid, 256, SMEM_TOTAL>>>(xs, spk, out);
}